// round 12
// baseline (speedup 1.0000x reference)
#include <cuda_runtime.h>
#include <cuda_fp16.h>
#include <cstdint>

// ---------------------------------------------------------------------------
// ViewGCNEncoder: 3-layer GCN.  (R11 + double-buffered pipelined GEMM k-loop)
//   per layer: h = A_in @ W^T + b  (fp16 A x fp16-split W, m16n8k16 mma,
//                                   fp16 output)
//              s = SpMM(adj, h)    (CSR segment-sum; gathers fp16, accum fp32)
//              s = leaky_relu(s); s = mask ? s*1.25 : 0   (layers 1,2 only)
// ---------------------------------------------------------------------------

#define NMAX 50000
#define EMAX 800000

__device__ __half g_h16[(size_t)NMAX * 256];   // GEMM outputs (gather target)
__device__ float  g_bufB[(size_t)NMAX * 256];  // SpMM outputs (GEMM inputs)
__device__ int    g_cnt[NMAX];
__device__ int    g_rowptr[NMAX + 1];
__device__ int    g_cursor[NMAX];
__device__ int2   g_edge[EMAX];                // packed {col, val_bits}

// ---------------------------------------------------------------------------
// CSR construction
// ---------------------------------------------------------------------------
__global__ void hist_kernel(const int* __restrict__ rows, int E) {
    int i = blockIdx.x * blockDim.x + threadIdx.x;
    if (i < E) atomicAdd(&g_cnt[rows[i]], 1);
}

__global__ void scan_kernel(int n) {
    __shared__ int partial[1024];
    int tid = threadIdx.x;
    int chunk = (n + 1023) >> 10;
    int beg = tid * chunk;
    int end = min(beg + chunk, n);
    int sum = 0;
    for (int i = beg; i < end; ++i) sum += g_cnt[i];
    partial[tid] = sum;
    __syncthreads();
    for (int d = 1; d < 1024; d <<= 1) {
        int add = (tid >= d) ? partial[tid - d] : 0;
        __syncthreads();
        partial[tid] += add;
        __syncthreads();
    }
    int run = partial[tid] - sum;
    for (int i = beg; i < end; ++i) {
        g_rowptr[i] = run;
        g_cursor[i] = run;
        run += g_cnt[i];
    }
    if (beg < n && end == n) g_rowptr[n] = run;
}

__global__ void scatter_kernel(const int* __restrict__ rows, const int* __restrict__ cols,
                               const float* __restrict__ vals, int E) {
    int i = blockIdx.x * blockDim.x + threadIdx.x;
    if (i < E) {
        int r = rows[i];
        int pos = atomicAdd(&g_cursor[r], 1);
        g_edge[pos] = make_int2(cols[i], __float_as_int(vals[i]));
    }
}

// ---------------------------------------------------------------------------
// 2-term fp16 tensor-core GEMM: C[N,ODIM] = A[N,KDIM] @ W[ODIM,KDIM]^T + bias
// A rounded to fp16 (Ah); W split hi+lo. C += Ah*Wh + Ah*Wl.
// BM=128, BK=16, BN = NTH/4. Double-buffered smem: next tile's LDG overlaps
// the current tile's mma; ONE barrier per k-iteration.
// ---------------------------------------------------------------------------
__device__ __forceinline__ void mma_f16(float c[4], const uint32_t a[4], const uint32_t b[2]) {
    asm volatile(
        "mma.sync.aligned.m16n8k16.row.col.f32.f16.f16.f32 "
        "{%0,%1,%2,%3},{%4,%5,%6,%7},{%8,%9},{%0,%1,%2,%3};"
        : "+f"(c[0]), "+f"(c[1]), "+f"(c[2]), "+f"(c[3])
        : "r"(a[0]), "r"(a[1]), "r"(a[2]), "r"(a[3]),
          "r"(b[0]), "r"(b[1]));
}

__device__ __forceinline__ void split2(float x, __half& hi, __half& lo) {
    hi = __float2half_rn(x);
    lo = __float2half_rn(x - __half2float(hi));
}

template <int KDIM, int ODIM, int NTH>
__global__ __launch_bounds__(NTH, 1024 / NTH) void gemm_tc_kernel(
    const float* __restrict__ A, const float* __restrict__ W,
    const float* __restrict__ bias, __half* __restrict__ C, int N)
{
    constexpr int BM = 128, BK = 16, BK2 = BK / 2;
    constexpr int BN = NTH / 4;
    constexpr int AREPS = BM / (NTH / 4);
    constexpr int ASTR = BM + 8;
    constexpr int BSTR = BN + 8;

    __shared__ __half2 As_hi[2][BK2][ASTR];
    __shared__ __half2 Ws_hi[2][BK2][BSTR];
    __shared__ __half2 Ws_lo[2][BK2][BSTR];

    const int tid  = threadIdx.x;
    const int m0   = blockIdx.x * BM;
    const int o0   = blockIdx.y * BN;
    const int warp = tid >> 5;
    const int lane = tid & 31;
    const int g    = lane >> 2;
    const int t4   = lane & 3;
    const int wm   = warp & 3;
    const int wn   = warp >> 2;

    const int ldm = tid >> 2;
    const int ldq = tid & 3;

    float acc[2][4][4];
#pragma unroll
    for (int mt = 0; mt < 2; ++mt)
#pragma unroll
        for (int nt = 0; nt < 4; ++nt)
#pragma unroll
            for (int i = 0; i < 4; ++i) acc[mt][nt][i] = 0.f;

    // ---- tile load helpers (regs only) ----
    float4 av[AREPS], wv;
    auto load_tile = [&](int k0) {
#pragma unroll
        for (int rep = 0; rep < AREPS; ++rep) {
            int m = m0 + ldm + rep * (NTH / 4);
            av[rep] = make_float4(0.f, 0.f, 0.f, 0.f);
            if (m < N) av[rep] = *(const float4*)&A[(size_t)m * KDIM + k0 + ldq * 4];
        }
        wv = *(const float4*)&W[(size_t)(o0 + ldm) * KDIM + k0 + ldq * 4];
    };
    auto store_tile = [&](int buf) {
#pragma unroll
        for (int rep = 0; rep < AREPS; ++rep) {
            int mrow = ldm + rep * (NTH / 4);
            As_hi[buf][ldq * 2 + 0][mrow] =
                __halves2half2(__float2half_rn(av[rep].x), __float2half_rn(av[rep].y));
            As_hi[buf][ldq * 2 + 1][mrow] =
                __halves2half2(__float2half_rn(av[rep].z), __float2half_rn(av[rep].w));
        }
        __half hx, lx, hy, ly, hz, lz, hw, lw;
        split2(wv.x, hx, lx); split2(wv.y, hy, ly);
        split2(wv.z, hz, lz); split2(wv.w, hw, lw);
        Ws_hi[buf][ldq * 2 + 0][ldm] = __halves2half2(hx, hy);
        Ws_lo[buf][ldq * 2 + 0][ldm] = __halves2half2(lx, ly);
        Ws_hi[buf][ldq * 2 + 1][ldm] = __halves2half2(hz, hw);
        Ws_lo[buf][ldq * 2 + 1][ldm] = __halves2half2(lz, lw);
    };

    // prologue: fill buffer 0
    load_tile(0);
    store_tile(0);
    __syncthreads();

    int cur = 0;
    for (int k0 = 0; k0 < KDIM; k0 += BK) {
        // prefetch next tile's gmem data FIRST (overlaps with mma below)
        const bool has_next = (k0 + BK) < KDIM;
        if (has_next) load_tile(k0 + BK);

        // fragments from current buffer + mma
        uint32_t a_hi[2][4];
#pragma unroll
        for (int mt = 0; mt < 2; ++mt) {
            int mb = wm * 32 + mt * 16 + g;
            a_hi[mt][0] = *(const uint32_t*)&As_hi[cur][t4][mb];
            a_hi[mt][1] = *(const uint32_t*)&As_hi[cur][t4][mb + 8];
            a_hi[mt][2] = *(const uint32_t*)&As_hi[cur][t4 + 4][mb];
            a_hi[mt][3] = *(const uint32_t*)&As_hi[cur][t4 + 4][mb + 8];
        }
        uint32_t b_hi[4][2], b_lo[4][2];
#pragma unroll
        for (int nt = 0; nt < 4; ++nt) {
            int nb = wn * 32 + nt * 8 + g;
            b_hi[nt][0] = *(const uint32_t*)&Ws_hi[cur][t4][nb];
            b_hi[nt][1] = *(const uint32_t*)&Ws_hi[cur][t4 + 4][nb];
            b_lo[nt][0] = *(const uint32_t*)&Ws_lo[cur][t4][nb];
            b_lo[nt][1] = *(const uint32_t*)&Ws_lo[cur][t4 + 4][nb];
        }
#pragma unroll
        for (int mt = 0; mt < 2; ++mt)
#pragma unroll
            for (int nt = 0; nt < 4; ++nt) {
                mma_f16(acc[mt][nt], a_hi[mt], b_hi[nt]);
                mma_f16(acc[mt][nt], a_hi[mt], b_lo[nt]);
            }

        // stage next tile into the other buffer; single barrier per iter
        if (has_next) {
            store_tile(1 - cur);
            __syncthreads();
            cur ^= 1;
        }
    }

#pragma unroll
    for (int mt = 0; mt < 2; ++mt) {
        int row0 = m0 + wm * 32 + mt * 16 + g;
#pragma unroll
        for (int nt = 0; nt < 4; ++nt) {
            int col = o0 + wn * 32 + nt * 8 + 2 * t4;
            float2 bv = *(const float2*)&bias[col];
            if (row0 < N) {
                __half2 o = __float22half2_rn(
                    make_float2(acc[mt][nt][0] + bv.x, acc[mt][nt][1] + bv.y));
                *(__half2*)&C[(size_t)row0 * ODIM + col] = o;
            }
            if (row0 + 8 < N) {
                __half2 o = __float22half2_rn(
                    make_float2(acc[mt][nt][2] + bv.x, acc[mt][nt][3] + bv.y));
                *(__half2*)&C[(size_t)(row0 + 8) * ODIM + col] = o;
            }
        }
    }
}

// ---------------------------------------------------------------------------
// CSR SpMM, warp-per-row, atomic-free. Smem-staged edge batches, LDS
// broadcast. Gathers fp16, accumulates fp32, fused LeakyReLU + dropout mask.
// ---------------------------------------------------------------------------
__device__ __forceinline__ float leaky(float x) { return x >= 0.f ? x : 0.2f * x; }

template <int D, bool HAS_MASK>
__global__ __launch_bounds__(256) void spmm_kernel(
    const __half* __restrict__ H, const unsigned int* __restrict__ mask,
    float* __restrict__ out, int N)
{
    __shared__ int2 ebuf[8][32];

    const int wid  = threadIdx.x >> 5;
    const int lane = threadIdx.x & 31;
    const int r    = blockIdx.x * 8 + wid;
    if (r >= N) return;
    const int start = g_rowptr[r];
    const int end   = g_rowptr[r + 1];

    constexpr int V = D / 32;
    float acc[V];
#pragma unroll
    for (int v = 0; v < V; ++v) acc[v] = 0.f;

    for (int base = start; base < end; base += 32) {
        int e = base + lane;
        if (e < end) ebuf[wid][lane] = g_edge[e];
        __syncwarp();
        int cnt = min(32, end - base);
#pragma unroll 8
        for (int j = 0; j < cnt; ++j) {
            int2  u  = ebuf[wid][j];
            float vj = __int_as_float(u.y);
            const __half* hp = H + (size_t)u.x * D + lane * V;
            if (D == 256) {
                uint4 raw = *(const uint4*)hp;
                float2 f0 = __half22float2(*(const __half2*)&raw.x);
                float2 f1 = __half22float2(*(const __half2*)&raw.y);
                float2 f2 = __half22float2(*(const __half2*)&raw.z);
                float2 f3 = __half22float2(*(const __half2*)&raw.w);
                acc[0] += vj * f0.x; acc[1] += vj * f0.y;
                acc[2] += vj * f1.x; acc[3] += vj * f1.y;
                acc[4] += vj * f2.x; acc[5] += vj * f2.y;
                acc[6] += vj * f3.x; acc[7] += vj * f3.y;
            } else if (D == 128) {
                uint2 raw = *(const uint2*)hp;
                float2 f0 = __half22float2(*(const __half2*)&raw.x);
                float2 f1 = __half22float2(*(const __half2*)&raw.y);
                acc[0] += vj * f0.x; acc[1] += vj * f0.y;
                acc[2] += vj * f1.x; acc[3] += vj * f1.y;
            } else {
                uint32_t raw = *(const uint32_t*)hp;
                float2 f0 = __half22float2(*(const __half2*)&raw);
                acc[0] += vj * f0.x; acc[1] += vj * f0.y;
            }
        }
        __syncwarp();
    }

    const float keep = 1.25f;
    float* op = out + (size_t)r * D + lane * V;
    if (D == 256) {
        float4 o0, o1;
        if (HAS_MASK) {
            const unsigned int* mp = mask + (size_t)r * D + lane * V;
            uint4 m0 = __ldcs((const uint4*)mp);
            uint4 m1 = __ldcs((const uint4*)(mp + 4));
            o0.x = m0.x ? leaky(acc[0]) * keep : 0.f;
            o0.y = m0.y ? leaky(acc[1]) * keep : 0.f;
            o0.z = m0.z ? leaky(acc[2]) * keep : 0.f;
            o0.w = m0.w ? leaky(acc[3]) * keep : 0.f;
            o1.x = m1.x ? leaky(acc[4]) * keep : 0.f;
            o1.y = m1.y ? leaky(acc[5]) * keep : 0.f;
            o1.z = m1.z ? leaky(acc[6]) * keep : 0.f;
            o1.w = m1.w ? leaky(acc[7]) * keep : 0.f;
        } else {
            o0 = make_float4(acc[0], acc[1], acc[2], acc[3]);
            o1 = make_float4(acc[4], acc[5], acc[6], acc[7]);
        }
        *(float4*)op = o0;
        *(float4*)(op + 4) = o1;
    } else if (D == 128) {
        float4 o0;
        if (HAS_MASK) {
            uint4 m0 = __ldcs((const uint4*)(mask + (size_t)r * D + lane * V));
            o0.x = m0.x ? leaky(acc[0]) * keep : 0.f;
            o0.y = m0.y ? leaky(acc[1]) * keep : 0.f;
            o0.z = m0.z ? leaky(acc[2]) * keep : 0.f;
            o0.w = m0.w ? leaky(acc[3]) * keep : 0.f;
        } else {
            o0 = make_float4(acc[0], acc[1], acc[2], acc[3]);
        }
        *(float4*)op = o0;
    } else {
        __stcs((float2*)op, make_float2(acc[0], acc[1]));
    }
}

// ---------------------------------------------------------------------------
// Launch.  CSR build forked onto a side stream, overlapping GEMM1.
// ---------------------------------------------------------------------------
extern "C" void kernel_launch(void* const* d_in, const int* in_sizes, int n_in,
                              void* d_out, int out_size)
{
    const float* x     = (const float*)d_in[0];
    const int*   rows  = (const int*)d_in[1];
    const int*   cols  = (const int*)d_in[2];
    const float* vals  = (const float*)d_in[3];
    const float* W1    = (const float*)d_in[4];
    const float* b1    = (const float*)d_in[5];
    const float* W2    = (const float*)d_in[6];
    const float* b2    = (const float*)d_in[7];
    const float* W3    = (const float*)d_in[8];
    const float* b3    = (const float*)d_in[9];
    const unsigned int* mask1 = (const unsigned int*)d_in[10];
    const unsigned int* mask2 = (const unsigned int*)d_in[11];
    float* out = (float*)d_out;

    const int N = in_sizes[0] / 256;
    const int E = in_sizes[1];

    void *pH = nullptr, *pB = nullptr, *pCnt = nullptr;
    cudaGetSymbolAddress(&pH, g_h16);
    cudaGetSymbolAddress(&pB, g_bufB);
    cudaGetSymbolAddress(&pCnt, g_cnt);
    __half* h16  = (__half*)pH;
    float*  bufB = (float*)pB;

    static cudaStream_t s2 = nullptr;
    static cudaEvent_t evFork = nullptr, evJoin = nullptr;
    if (s2 == nullptr) {
        cudaStreamCreateWithFlags(&s2, cudaStreamNonBlocking);
        cudaEventCreateWithFlags(&evFork, cudaEventDisableTiming);
        cudaEventCreateWithFlags(&evJoin, cudaEventDisableTiming);
    }

    // Fork: CSR build on s2, GEMM1 on the main stream.
    cudaEventRecord(evFork, 0);
    cudaStreamWaitEvent(s2, evFork, 0);

    cudaMemsetAsync(pCnt, 0, (size_t)N * sizeof(int), s2);
    hist_kernel<<<(E + 255) / 256, 256, 0, s2>>>(rows, E);
    scan_kernel<<<1, 1024, 0, s2>>>(N);
    scatter_kernel<<<(E + 255) / 256, 256, 0, s2>>>(rows, cols, vals, E);
    cudaEventRecord(evJoin, s2);

    // GEMM1 on main stream (overlaps the CSR build)
    dim3 g1((N + 127) / 128, 256 / 128);
    gemm_tc_kernel<256, 256, 512><<<g1, 512>>>(x, W1, b1, h16, N);

    // Join: SpMM1 needs both GEMM1 and the CSR.
    cudaStreamWaitEvent(0, evJoin, 0);
    spmm_kernel<256, true><<<(N + 7) / 8, 256>>>(h16, mask1, bufB, N);

    // Layer 2: 256 -> 128
    dim3 g2((N + 127) / 128, 1);
    gemm_tc_kernel<256, 128, 512><<<g2, 512>>>(bufB, W2, b2, h16, N);
    spmm_kernel<128, true><<<(N + 7) / 8, 256>>>(h16, mask2, bufB, N);

    // Layer 3: 128 -> 64
    dim3 g3((N + 127) / 128, 1);
    gemm_tc_kernel<128, 64, 256><<<g3, 256>>>(bufB, W3, b3, h16, N);
    spmm_kernel<64, false><<<(N + 7) / 8, 256>>>(h16, (const unsigned int*)nullptr, out, N);
}

// round 16
// speedup vs baseline: 1.2203x; 1.2203x over previous
#include <cuda_runtime.h>
#include <cuda_fp16.h>
#include <cstdint>

// ---------------------------------------------------------------------------
// ViewGCNEncoder: 3-layer GCN.  (R11 structure; pure-fp16 GEMM hot loop:
// W pre-split to hi/lo once, x pre-converted to fp16, SpMM emits fp16.)
//   per layer: h = A16 @ (Wh+Wl)^T + b  (2-term m16n8k16 mma, fp16 output)
//              s = SpMM(adj, h)  (CSR segment-sum; gathers fp16, accum fp32)
//              s = leaky_relu(s); s = mask ? s*1.25 : 0   (layers 1,2 only)
// ---------------------------------------------------------------------------

#define NMAX 50000
#define EMAX 800000

__device__ __half g_h16[(size_t)NMAX * 256];   // GEMM outputs (gather target)
__device__ __half g_a16[(size_t)NMAX * 256];   // GEMM inputs (x16 / SpMM out)
__device__ __half g_Wh[106496];                // W1|W2|W3 hi (65536|32768|8192)
__device__ __half g_Wl[106496];                // W1|W2|W3 lo
__device__ int    g_cnt[NMAX];
__device__ int    g_rowptr[NMAX + 1];
__device__ int    g_cursor[NMAX];
__device__ int2   g_edge[EMAX];                // packed {col, val_bits}

// ---------------------------------------------------------------------------
// One-time conversions
// ---------------------------------------------------------------------------
__global__ void split_w_kernel(const float* __restrict__ in,
                               __half* __restrict__ hi, __half* __restrict__ lo,
                               int n4) {
    int i = blockIdx.x * blockDim.x + threadIdx.x;
    if (i >= n4) return;
    float4 v = ((const float4*)in)[i];
    __half hx = __float2half_rn(v.x), hy = __float2half_rn(v.y);
    __half hz = __float2half_rn(v.z), hw = __float2half_rn(v.w);
    __half lx = __float2half_rn(v.x - __half2float(hx));
    __half ly = __float2half_rn(v.y - __half2float(hy));
    __half lz = __float2half_rn(v.z - __half2float(hz));
    __half lw = __float2half_rn(v.w - __half2float(hw));
    __half2 h0 = __halves2half2(hx, hy), h1 = __halves2half2(hz, hw);
    __half2 l0 = __halves2half2(lx, ly), l1 = __halves2half2(lz, lw);
    ((uint2*)hi)[i] = make_uint2(*(uint32_t*)&h0, *(uint32_t*)&h1);
    ((uint2*)lo)[i] = make_uint2(*(uint32_t*)&l0, *(uint32_t*)&l1);
}

__global__ void cvt16_kernel(const float* __restrict__ in,
                             __half* __restrict__ out, int n4) {
    int i = blockIdx.x * blockDim.x + threadIdx.x;
    if (i >= n4) return;
    float4 v = ((const float4*)in)[i];
    __half2 h0 = __floats2half2_rn(v.x, v.y);
    __half2 h1 = __floats2half2_rn(v.z, v.w);
    ((uint2*)out)[i] = make_uint2(*(uint32_t*)&h0, *(uint32_t*)&h1);
}

// ---------------------------------------------------------------------------
// CSR construction
// ---------------------------------------------------------------------------
__global__ void hist_kernel(const int* __restrict__ rows, int E) {
    int i = blockIdx.x * blockDim.x + threadIdx.x;
    if (i < E) atomicAdd(&g_cnt[rows[i]], 1);
}

__global__ void scan_kernel(int n) {
    __shared__ int partial[1024];
    int tid = threadIdx.x;
    int chunk = (n + 1023) >> 10;
    int beg = tid * chunk;
    int end = min(beg + chunk, n);
    int sum = 0;
    for (int i = beg; i < end; ++i) sum += g_cnt[i];
    partial[tid] = sum;
    __syncthreads();
    for (int d = 1; d < 1024; d <<= 1) {
        int add = (tid >= d) ? partial[tid - d] : 0;
        __syncthreads();
        partial[tid] += add;
        __syncthreads();
    }
    int run = partial[tid] - sum;
    for (int i = beg; i < end; ++i) {
        g_rowptr[i] = run;
        g_cursor[i] = run;
        run += g_cnt[i];
    }
    if (beg < n && end == n) g_rowptr[n] = run;
}

__global__ void scatter_kernel(const int* __restrict__ rows, const int* __restrict__ cols,
                               const float* __restrict__ vals, int E) {
    int i = blockIdx.x * blockDim.x + threadIdx.x;
    if (i < E) {
        int r = rows[i];
        int pos = atomicAdd(&g_cursor[r], 1);
        g_edge[pos] = make_int2(cols[i], __float_as_int(vals[i]));
    }
}

// ---------------------------------------------------------------------------
// 2-term fp16 tensor-core GEMM: C[N,ODIM] = A16 @ (Wh+Wl)[ODIM,KDIM]^T + bias
// All inputs fp16; hot loop has NO conversions.
// BM=128, BK=16, BN = NTH/4. Per-warp 32x32 tile, m16n8k16 mma.
// ---------------------------------------------------------------------------
__device__ __forceinline__ void mma_f16(float c[4], const uint32_t a[4], const uint32_t b[2]) {
    asm volatile(
        "mma.sync.aligned.m16n8k16.row.col.f32.f16.f16.f32 "
        "{%0,%1,%2,%3},{%4,%5,%6,%7},{%8,%9},{%0,%1,%2,%3};"
        : "+f"(c[0]), "+f"(c[1]), "+f"(c[2]), "+f"(c[3])
        : "r"(a[0]), "r"(a[1]), "r"(a[2]), "r"(a[3]),
          "r"(b[0]), "r"(b[1]));
}

template <int KDIM, int ODIM, int NTH>
__global__ __launch_bounds__(NTH, 1024 / NTH) void gemm_tc_kernel(
    const __half* __restrict__ A, const __half* __restrict__ Wh,
    const __half* __restrict__ Wl,
    const float* __restrict__ bias, __half* __restrict__ C, int N)
{
    constexpr int BM = 128, BK = 16, BK2 = BK / 2;
    constexpr int BN = NTH / 4;
    constexpr int AREPS = BM / (NTH / 4);
    constexpr int ASTR = BM + 8;
    constexpr int BSTR = BN + 8;

    __shared__ __half2 As_hi[BK2][ASTR];
    __shared__ __half2 Ws_hi[BK2][BSTR];
    __shared__ __half2 Ws_lo[BK2][BSTR];

    const int tid  = threadIdx.x;
    const int m0   = blockIdx.x * BM;
    const int o0   = blockIdx.y * BN;
    const int warp = tid >> 5;
    const int lane = tid & 31;
    const int g    = lane >> 2;
    const int t4   = lane & 3;
    const int wm   = warp & 3;
    const int wn   = warp >> 2;

    const int ldm = tid >> 2;       // row (0..NTH/4-1); 4 threads per row
    const int ldq = tid & 3;        // 4-half chunk index along k

    float acc[2][4][4];
#pragma unroll
    for (int mt = 0; mt < 2; ++mt)
#pragma unroll
        for (int nt = 0; nt < 4; ++nt)
#pragma unroll
            for (int i = 0; i < 4; ++i) acc[mt][nt][i] = 0.f;

    for (int k0 = 0; k0 < KDIM; k0 += BK) {
        // A tile 128x16 halves (uint2 = 4 halves per thread per rep)
#pragma unroll
        for (int rep = 0; rep < AREPS; ++rep) {
            int mrow = ldm + rep * (NTH / 4);
            int m = m0 + mrow;
            uint2 v = make_uint2(0, 0);
            if (m < N) v = *(const uint2*)&A[(size_t)m * KDIM + k0 + ldq * 4];
            As_hi[ldq * 2 + 0][mrow] = *(__half2*)&v.x;
            As_hi[ldq * 2 + 1][mrow] = *(__half2*)&v.y;
        }
        // W tiles BNx16 halves (hi + lo)
        {
            uint2 vh = *(const uint2*)&Wh[(size_t)(o0 + ldm) * KDIM + k0 + ldq * 4];
            uint2 vl = *(const uint2*)&Wl[(size_t)(o0 + ldm) * KDIM + k0 + ldq * 4];
            Ws_hi[ldq * 2 + 0][ldm] = *(__half2*)&vh.x;
            Ws_hi[ldq * 2 + 1][ldm] = *(__half2*)&vh.y;
            Ws_lo[ldq * 2 + 0][ldm] = *(__half2*)&vl.x;
            Ws_lo[ldq * 2 + 1][ldm] = *(__half2*)&vl.y;
        }
        __syncthreads();

        uint32_t a_hi[2][4];
#pragma unroll
        for (int mt = 0; mt < 2; ++mt) {
            int mb = wm * 32 + mt * 16 + g;
            a_hi[mt][0] = *(const uint32_t*)&As_hi[t4][mb];
            a_hi[mt][1] = *(const uint32_t*)&As_hi[t4][mb + 8];
            a_hi[mt][2] = *(const uint32_t*)&As_hi[t4 + 4][mb];
            a_hi[mt][3] = *(const uint32_t*)&As_hi[t4 + 4][mb + 8];
        }
        uint32_t b_hi[4][2], b_lo[4][2];
#pragma unroll
        for (int nt = 0; nt < 4; ++nt) {
            int nb = wn * 32 + nt * 8 + g;
            b_hi[nt][0] = *(const uint32_t*)&Ws_hi[t4][nb];
            b_hi[nt][1] = *(const uint32_t*)&Ws_hi[t4 + 4][nb];
            b_lo[nt][0] = *(const uint32_t*)&Ws_lo[t4][nb];
            b_lo[nt][1] = *(const uint32_t*)&Ws_lo[t4 + 4][nb];
        }
#pragma unroll
        for (int mt = 0; mt < 2; ++mt)
#pragma unroll
            for (int nt = 0; nt < 4; ++nt) {
                mma_f16(acc[mt][nt], a_hi[mt], b_hi[nt]);
                mma_f16(acc[mt][nt], a_hi[mt], b_lo[nt]);
            }
        __syncthreads();
    }

#pragma unroll
    for (int mt = 0; mt < 2; ++mt) {
        int row0 = m0 + wm * 32 + mt * 16 + g;
#pragma unroll
        for (int nt = 0; nt < 4; ++nt) {
            int col = o0 + wn * 32 + nt * 8 + 2 * t4;
            float2 bv = *(const float2*)&bias[col];
            if (row0 < N) {
                __half2 o = __float22half2_rn(
                    make_float2(acc[mt][nt][0] + bv.x, acc[mt][nt][1] + bv.y));
                *(__half2*)&C[(size_t)row0 * ODIM + col] = o;
            }
            if (row0 + 8 < N) {
                __half2 o = __float22half2_rn(
                    make_float2(acc[mt][nt][2] + bv.x, acc[mt][nt][3] + bv.y));
                *(__half2*)&C[(size_t)(row0 + 8) * ODIM + col] = o;
            }
        }
    }
}

// ---------------------------------------------------------------------------
// CSR SpMM, warp-per-row, atomic-free. Smem-staged edge batches. Gathers
// fp16, accumulates fp32, fused LeakyReLU + dropout mask. Layers 1-2 emit
// fp16 (next GEMM's A, rounded identically to the old in-GEMM cvt); the
// final layer writes fp32 to d_out.
// ---------------------------------------------------------------------------
__device__ __forceinline__ float leaky(float x) { return x >= 0.f ? x : 0.2f * x; }

template <int D, bool HAS_MASK, bool OUT16>
__global__ __launch_bounds__(256) void spmm_kernel(
    const __half* __restrict__ H, const unsigned int* __restrict__ mask,
    __half* __restrict__ out16, float* __restrict__ outF, int N)
{
    __shared__ int2 ebuf[8][32];

    const int wid  = threadIdx.x >> 5;
    const int lane = threadIdx.x & 31;
    const int r    = blockIdx.x * 8 + wid;
    if (r >= N) return;
    const int start = g_rowptr[r];
    const int end   = g_rowptr[r + 1];

    constexpr int V = D / 32;
    float acc[V];
#pragma unroll
    for (int v = 0; v < V; ++v) acc[v] = 0.f;

    for (int base = start; base < end; base += 32) {
        int e = base + lane;
        if (e < end) ebuf[wid][lane] = g_edge[e];
        __syncwarp();
        int cnt = min(32, end - base);
#pragma unroll 8
        for (int j = 0; j < cnt; ++j) {
            int2  u  = ebuf[wid][j];
            float vj = __int_as_float(u.y);
            const __half* hp = H + (size_t)u.x * D + lane * V;
            if (D == 256) {
                uint4 raw = *(const uint4*)hp;
                float2 f0 = __half22float2(*(const __half2*)&raw.x);
                float2 f1 = __half22float2(*(const __half2*)&raw.y);
                float2 f2 = __half22float2(*(const __half2*)&raw.z);
                float2 f3 = __half22float2(*(const __half2*)&raw.w);
                acc[0] += vj * f0.x; acc[1] += vj * f0.y;
                acc[2] += vj * f1.x; acc[3] += vj * f1.y;
                acc[4] += vj * f2.x; acc[5] += vj * f2.y;
                acc[6] += vj * f3.x; acc[7] += vj * f3.y;
            } else if (D == 128) {
                uint2 raw = *(const uint2*)hp;
                float2 f0 = __half22float2(*(const __half2*)&raw.x);
                float2 f1 = __half22float2(*(const __half2*)&raw.y);
                acc[0] += vj * f0.x; acc[1] += vj * f0.y;
                acc[2] += vj * f1.x; acc[3] += vj * f1.y;
            } else {
                uint32_t raw = *(const uint32_t*)hp;
                float2 f0 = __half22float2(*(const __half2*)&raw);
                acc[0] += vj * f0.x; acc[1] += vj * f0.y;
            }
        }
        __syncwarp();
    }

    const float keep = 1.25f;
    if (HAS_MASK) {
        unsigned int mv[V];
        const unsigned int* mp = mask + (size_t)r * D + lane * V;
        if (V == 8) {
            uint4 m0 = __ldcs((const uint4*)mp);
            uint4 m1 = __ldcs((const uint4*)(mp + 4));
            mv[0] = m0.x; mv[1] = m0.y; mv[2] = m0.z; mv[3] = m0.w;
            mv[4] = m1.x; mv[5] = m1.y; mv[6] = m1.z; mv[7] = m1.w;
        } else if (V == 4) {
            uint4 m0 = __ldcs((const uint4*)mp);
            mv[0] = m0.x; mv[1] = m0.y; mv[2] = m0.z; mv[3] = m0.w;
        } else {
            uint2 m0 = __ldcs((const uint2*)mp);
            mv[0] = m0.x; mv[1] = m0.y;
        }
#pragma unroll
        for (int v = 0; v < V; ++v)
            acc[v] = mv[v] ? leaky(acc[v]) * keep : 0.f;
    }

    if (OUT16) {
        __half2 hh[V / 2];
#pragma unroll
        for (int p = 0; p < V / 2; ++p)
            hh[p] = __floats2half2_rn(acc[2 * p], acc[2 * p + 1]);
        size_t off = (size_t)r * D + lane * V;
        if (V == 8)      *(uint4*)&out16[off] = *(uint4*)hh;
        else if (V == 4) *(uint2*)&out16[off] = *(uint2*)hh;
        else             *(uint32_t*)&out16[off] = *(uint32_t*)hh;
    } else {
        float* op = outF + (size_t)r * D + lane * V;
        if (V == 2) {
            __stcs((float2*)op, make_float2(acc[0], acc[1]));
        } else {
#pragma unroll
            for (int p = 0; p < V / 4; ++p)
                __stcs((float4*)(op + 4 * p),
                       make_float4(acc[4 * p], acc[4 * p + 1],
                                   acc[4 * p + 2], acc[4 * p + 3]));
        }
    }
}

// ---------------------------------------------------------------------------
// Launch.  CSR build forked onto a side stream, overlapping x/W conversion
// and GEMM1.
// ---------------------------------------------------------------------------
extern "C" void kernel_launch(void* const* d_in, const int* in_sizes, int n_in,
                              void* d_out, int out_size)
{
    const float* x     = (const float*)d_in[0];
    const int*   rows  = (const int*)d_in[1];
    const int*   cols  = (const int*)d_in[2];
    const float* vals  = (const float*)d_in[3];
    const float* W1    = (const float*)d_in[4];
    const float* b1    = (const float*)d_in[5];
    const float* W2    = (const float*)d_in[6];
    const float* b2    = (const float*)d_in[7];
    const float* W3    = (const float*)d_in[8];
    const float* b3    = (const float*)d_in[9];
    const unsigned int* mask1 = (const unsigned int*)d_in[10];
    const unsigned int* mask2 = (const unsigned int*)d_in[11];
    float* out = (float*)d_out;

    const int N = in_sizes[0] / 256;
    const int E = in_sizes[1];

    void *pH = nullptr, *pA = nullptr, *pWh = nullptr, *pWl = nullptr, *pCnt = nullptr;
    cudaGetSymbolAddress(&pH, g_h16);
    cudaGetSymbolAddress(&pA, g_a16);
    cudaGetSymbolAddress(&pWh, g_Wh);
    cudaGetSymbolAddress(&pWl, g_Wl);
    cudaGetSymbolAddress(&pCnt, g_cnt);
    __half* h16 = (__half*)pH;
    __half* a16 = (__half*)pA;
    __half* Wh  = (__half*)pWh;
    __half* Wl  = (__half*)pWl;

    static cudaStream_t s2 = nullptr;
    static cudaEvent_t evFork = nullptr, evJoin = nullptr;
    if (s2 == nullptr) {
        cudaStreamCreateWithFlags(&s2, cudaStreamNonBlocking);
        cudaEventCreateWithFlags(&evFork, cudaEventDisableTiming);
        cudaEventCreateWithFlags(&evJoin, cudaEventDisableTiming);
    }

    // Fork: CSR build on s2.
    cudaEventRecord(evFork, 0);
    cudaStreamWaitEvent(s2, evFork, 0);
    cudaMemsetAsync(pCnt, 0, (size_t)N * sizeof(int), s2);
    hist_kernel<<<(E + 255) / 256, 256, 0, s2>>>(rows, E);
    scan_kernel<<<1, 1024, 0, s2>>>(N);
    scatter_kernel<<<(E + 255) / 256, 256, 0, s2>>>(rows, cols, vals, E);
    cudaEventRecord(evJoin, s2);

    // Main stream: conversions, then GEMM1 (overlaps the CSR build)
    split_w_kernel<<<(65536 / 4 + 255) / 256, 256>>>(W1, Wh, Wl, 65536 / 4);
    split_w_kernel<<<(32768 / 4 + 255) / 256, 256>>>(W2, Wh + 65536, Wl + 65536, 32768 / 4);
    split_w_kernel<<<(8192 / 4 + 255) / 256, 256>>>(W3, Wh + 98304, Wl + 98304, 8192 / 4);
    {
        int n4 = N * 256 / 4;
        cvt16_kernel<<<(n4 + 255) / 256, 256>>>(x, a16, n4);
    }

    dim3 g1((N + 127) / 128, 256 / 128);
    gemm_tc_kernel<256, 256, 512><<<g1, 512>>>(a16, Wh, Wl, b1, h16, N);

    // Join: SpMM1 needs both GEMM1 and the CSR.
    cudaStreamWaitEvent(0, evJoin, 0);
    spmm_kernel<256, true, true><<<(N + 7) / 8, 256>>>(h16, mask1, a16, nullptr, N);

    // Layer 2: 256 -> 128
    dim3 g2((N + 127) / 128, 1);
    gemm_tc_kernel<256, 128, 512><<<g2, 512>>>(a16, Wh + 65536, Wl + 65536, b2, h16, N);
    spmm_kernel<128, true, true><<<(N + 7) / 8, 256>>>(h16, mask2, a16, nullptr, N);

    // Layer 3: 128 -> 64
    dim3 g3((N + 127) / 128, 1);
    gemm_tc_kernel<128, 64, 256><<<g3, 256>>>(a16, Wh + 98304, Wl + 98304, b3, h16, N);
    spmm_kernel<64, false, false><<<(N + 7) / 8, 256>>>(h16, nullptr, nullptr, out, N);
}

// round 17
// speedup vs baseline: 1.3058x; 1.0701x over previous
#include <cuda_runtime.h>
#include <cuda_fp16.h>
#include <cstdint>

// ---------------------------------------------------------------------------
// ViewGCNEncoder: 3-layer GCN.  (R16 + 1-term fp16 GEMM: W rounded to fp16,
// no lo-term; all GEMM operands plain fp16.)
//   per layer: h = A16 @ W16^T + b   (m16n8k16 mma, fp32 accum, fp16 output)
//              s = SpMM(adj, h)      (CSR segment-sum; fp16 gather, fp32 acc)
//              s = leaky_relu(s); s = mask ? s*1.25 : 0   (layers 1,2 only)
// ---------------------------------------------------------------------------

#define NMAX 50000
#define EMAX 800000

__device__ __half g_h16[(size_t)NMAX * 256];   // GEMM outputs (gather target)
__device__ __half g_a16[(size_t)NMAX * 256];   // GEMM inputs (x16 / SpMM out)
__device__ __half g_W16[106496];               // W1|W2|W3 fp16 (65536|32768|8192)
__device__ int    g_cnt[NMAX];
__device__ int    g_rowptr[NMAX + 1];
__device__ int    g_cursor[NMAX];
__device__ int2   g_edge[EMAX];                // packed {col, val_bits}

// ---------------------------------------------------------------------------
// One-time fp32 -> fp16 conversion
// ---------------------------------------------------------------------------
__global__ void cvt16_kernel(const float* __restrict__ in,
                             __half* __restrict__ out, int n4) {
    int i = blockIdx.x * blockDim.x + threadIdx.x;
    if (i >= n4) return;
    float4 v = ((const float4*)in)[i];
    __half2 h0 = __floats2half2_rn(v.x, v.y);
    __half2 h1 = __floats2half2_rn(v.z, v.w);
    ((uint2*)out)[i] = make_uint2(*(uint32_t*)&h0, *(uint32_t*)&h1);
}

// ---------------------------------------------------------------------------
// CSR construction
// ---------------------------------------------------------------------------
__global__ void hist_kernel(const int* __restrict__ rows, int E) {
    int i = blockIdx.x * blockDim.x + threadIdx.x;
    if (i < E) atomicAdd(&g_cnt[rows[i]], 1);
}

__global__ void scan_kernel(int n) {
    __shared__ int partial[1024];
    int tid = threadIdx.x;
    int chunk = (n + 1023) >> 10;
    int beg = tid * chunk;
    int end = min(beg + chunk, n);
    int sum = 0;
    for (int i = beg; i < end; ++i) sum += g_cnt[i];
    partial[tid] = sum;
    __syncthreads();
    for (int d = 1; d < 1024; d <<= 1) {
        int add = (tid >= d) ? partial[tid - d] : 0;
        __syncthreads();
        partial[tid] += add;
        __syncthreads();
    }
    int run = partial[tid] - sum;
    for (int i = beg; i < end; ++i) {
        g_rowptr[i] = run;
        g_cursor[i] = run;
        run += g_cnt[i];
    }
    if (beg < n && end == n) g_rowptr[n] = run;
}

__global__ void scatter_kernel(const int* __restrict__ rows, const int* __restrict__ cols,
                               const float* __restrict__ vals, int E) {
    int i = blockIdx.x * blockDim.x + threadIdx.x;
    if (i < E) {
        int r = rows[i];
        int pos = atomicAdd(&g_cursor[r], 1);
        g_edge[pos] = make_int2(cols[i], __float_as_int(vals[i]));
    }
}

// ---------------------------------------------------------------------------
// 1-term fp16 tensor-core GEMM: C[N,ODIM] = A16 @ W16[ODIM,KDIM]^T + bias
// All operands fp16, fp32 accumulate; hot loop = LDG/STS/LDS/mma only.
// BM=128, BK=16, BN = NTH/4. Per-warp 32x32 tile, m16n8k16 mma.
// ---------------------------------------------------------------------------
__device__ __forceinline__ void mma_f16(float c[4], const uint32_t a[4], const uint32_t b[2]) {
    asm volatile(
        "mma.sync.aligned.m16n8k16.row.col.f32.f16.f16.f32 "
        "{%0,%1,%2,%3},{%4,%5,%6,%7},{%8,%9},{%0,%1,%2,%3};"
        : "+f"(c[0]), "+f"(c[1]), "+f"(c[2]), "+f"(c[3])
        : "r"(a[0]), "r"(a[1]), "r"(a[2]), "r"(a[3]),
          "r"(b[0]), "r"(b[1]));
}

template <int KDIM, int ODIM, int NTH>
__global__ __launch_bounds__(NTH, 1024 / NTH) void gemm_tc_kernel(
    const __half* __restrict__ A, const __half* __restrict__ W16,
    const float* __restrict__ bias, __half* __restrict__ C, int N)
{
    constexpr int BM = 128, BK = 16, BK2 = BK / 2;
    constexpr int BN = NTH / 4;
    constexpr int AREPS = BM / (NTH / 4);
    constexpr int ASTR = BM + 8;
    constexpr int BSTR = BN + 8;

    __shared__ __half2 As[BK2][ASTR];
    __shared__ __half2 Ws[BK2][BSTR];

    const int tid  = threadIdx.x;
    const int m0   = blockIdx.x * BM;
    const int o0   = blockIdx.y * BN;
    const int warp = tid >> 5;
    const int lane = tid & 31;
    const int g    = lane >> 2;
    const int t4   = lane & 3;
    const int wm   = warp & 3;
    const int wn   = warp >> 2;

    const int ldm = tid >> 2;       // row (0..NTH/4-1); 4 threads per row
    const int ldq = tid & 3;        // 4-half chunk index along k

    float acc[2][4][4];
#pragma unroll
    for (int mt = 0; mt < 2; ++mt)
#pragma unroll
        for (int nt = 0; nt < 4; ++nt)
#pragma unroll
            for (int i = 0; i < 4; ++i) acc[mt][nt][i] = 0.f;

    for (int k0 = 0; k0 < KDIM; k0 += BK) {
        // A tile 128x16 halves
#pragma unroll
        for (int rep = 0; rep < AREPS; ++rep) {
            int mrow = ldm + rep * (NTH / 4);
            int m = m0 + mrow;
            uint2 v = make_uint2(0, 0);
            if (m < N) v = *(const uint2*)&A[(size_t)m * KDIM + k0 + ldq * 4];
            As[ldq * 2 + 0][mrow] = *(__half2*)&v.x;
            As[ldq * 2 + 1][mrow] = *(__half2*)&v.y;
        }
        // W tile BNx16 halves
        {
            uint2 v = *(const uint2*)&W16[(size_t)(o0 + ldm) * KDIM + k0 + ldq * 4];
            Ws[ldq * 2 + 0][ldm] = *(__half2*)&v.x;
            Ws[ldq * 2 + 1][ldm] = *(__half2*)&v.y;
        }
        __syncthreads();

        uint32_t a_f[2][4];
#pragma unroll
        for (int mt = 0; mt < 2; ++mt) {
            int mb = wm * 32 + mt * 16 + g;
            a_f[mt][0] = *(const uint32_t*)&As[t4][mb];
            a_f[mt][1] = *(const uint32_t*)&As[t4][mb + 8];
            a_f[mt][2] = *(const uint32_t*)&As[t4 + 4][mb];
            a_f[mt][3] = *(const uint32_t*)&As[t4 + 4][mb + 8];
        }
        uint32_t b_f[4][2];
#pragma unroll
        for (int nt = 0; nt < 4; ++nt) {
            int nb = wn * 32 + nt * 8 + g;
            b_f[nt][0] = *(const uint32_t*)&Ws[t4][nb];
            b_f[nt][1] = *(const uint32_t*)&Ws[t4 + 4][nb];
        }
#pragma unroll
        for (int mt = 0; mt < 2; ++mt)
#pragma unroll
            for (int nt = 0; nt < 4; ++nt)
                mma_f16(acc[mt][nt], a_f[mt], b_f[nt]);
        __syncthreads();
    }

#pragma unroll
    for (int mt = 0; mt < 2; ++mt) {
        int row0 = m0 + wm * 32 + mt * 16 + g;
#pragma unroll
        for (int nt = 0; nt < 4; ++nt) {
            int col = o0 + wn * 32 + nt * 8 + 2 * t4;
            float2 bv = *(const float2*)&bias[col];
            if (row0 < N) {
                __half2 o = __float22half2_rn(
                    make_float2(acc[mt][nt][0] + bv.x, acc[mt][nt][1] + bv.y));
                *(__half2*)&C[(size_t)row0 * ODIM + col] = o;
            }
            if (row0 + 8 < N) {
                __half2 o = __float22half2_rn(
                    make_float2(acc[mt][nt][2] + bv.x, acc[mt][nt][3] + bv.y));
                *(__half2*)&C[(size_t)(row0 + 8) * ODIM + col] = o;
            }
        }
    }
}

// ---------------------------------------------------------------------------
// CSR SpMM, warp-per-row, atomic-free. Smem-staged edge batches. Gathers
// fp16, accumulates fp32, fused LeakyReLU + dropout mask. Layers 1-2 emit
// fp16 (next GEMM's A); the final layer writes fp32 to d_out.
// ---------------------------------------------------------------------------
__device__ __forceinline__ float leaky(float x) { return x >= 0.f ? x : 0.2f * x; }

template <int D, bool HAS_MASK, bool OUT16>
__global__ __launch_bounds__(256) void spmm_kernel(
    const __half* __restrict__ H, const unsigned int* __restrict__ mask,
    __half* __restrict__ out16, float* __restrict__ outF, int N)
{
    __shared__ int2 ebuf[8][32];

    const int wid  = threadIdx.x >> 5;
    const int lane = threadIdx.x & 31;
    const int r    = blockIdx.x * 8 + wid;
    if (r >= N) return;
    const int start = g_rowptr[r];
    const int end   = g_rowptr[r + 1];

    constexpr int V = D / 32;
    float acc[V];
#pragma unroll
    for (int v = 0; v < V; ++v) acc[v] = 0.f;

    for (int base = start; base < end; base += 32) {
        int e = base + lane;
        if (e < end) ebuf[wid][lane] = g_edge[e];
        __syncwarp();
        int cnt = min(32, end - base);
#pragma unroll 8
        for (int j = 0; j < cnt; ++j) {
            int2  u  = ebuf[wid][j];
            float vj = __int_as_float(u.y);
            const __half* hp = H + (size_t)u.x * D + lane * V;
            if (D == 256) {
                uint4 raw = *(const uint4*)hp;
                float2 f0 = __half22float2(*(const __half2*)&raw.x);
                float2 f1 = __half22float2(*(const __half2*)&raw.y);
                float2 f2 = __half22float2(*(const __half2*)&raw.z);
                float2 f3 = __half22float2(*(const __half2*)&raw.w);
                acc[0] += vj * f0.x; acc[1] += vj * f0.y;
                acc[2] += vj * f1.x; acc[3] += vj * f1.y;
                acc[4] += vj * f2.x; acc[5] += vj * f2.y;
                acc[6] += vj * f3.x; acc[7] += vj * f3.y;
            } else if (D == 128) {
                uint2 raw = *(const uint2*)hp;
                float2 f0 = __half22float2(*(const __half2*)&raw.x);
                float2 f1 = __half22float2(*(const __half2*)&raw.y);
                acc[0] += vj * f0.x; acc[1] += vj * f0.y;
                acc[2] += vj * f1.x; acc[3] += vj * f1.y;
            } else {
                uint32_t raw = *(const uint32_t*)hp;
                float2 f0 = __half22float2(*(const __half2*)&raw);
                acc[0] += vj * f0.x; acc[1] += vj * f0.y;
            }
        }
        __syncwarp();
    }

    const float keep = 1.25f;
    if (HAS_MASK) {
        unsigned int mv[V];
        const unsigned int* mp = mask + (size_t)r * D + lane * V;
        if (V == 8) {
            uint4 m0 = __ldcs((const uint4*)mp);
            uint4 m1 = __ldcs((const uint4*)(mp + 4));
            mv[0] = m0.x; mv[1] = m0.y; mv[2] = m0.z; mv[3] = m0.w;
            mv[4] = m1.x; mv[5] = m1.y; mv[6] = m1.z; mv[7] = m1.w;
        } else if (V == 4) {
            uint4 m0 = __ldcs((const uint4*)mp);
            mv[0] = m0.x; mv[1] = m0.y; mv[2] = m0.z; mv[3] = m0.w;
        } else {
            uint2 m0 = __ldcs((const uint2*)mp);
            mv[0] = m0.x; mv[1] = m0.y;
        }
#pragma unroll
        for (int v = 0; v < V; ++v)
            acc[v] = mv[v] ? leaky(acc[v]) * keep : 0.f;
    }

    if (OUT16) {
        __half2 hh[V / 2];
#pragma unroll
        for (int p = 0; p < V / 2; ++p)
            hh[p] = __floats2half2_rn(acc[2 * p], acc[2 * p + 1]);
        size_t off = (size_t)r * D + lane * V;
        if (V == 8)      *(uint4*)&out16[off] = *(uint4*)hh;
        else if (V == 4) *(uint2*)&out16[off] = *(uint2*)hh;
        else             *(uint32_t*)&out16[off] = *(uint32_t*)hh;
    } else {
        float* op = outF + (size_t)r * D + lane * V;
        if (V == 2) {
            __stcs((float2*)op, make_float2(acc[0], acc[1]));
        } else {
#pragma unroll
            for (int p = 0; p < V / 4; ++p)
                __stcs((float4*)(op + 4 * p),
                       make_float4(acc[4 * p], acc[4 * p + 1],
                                   acc[4 * p + 2], acc[4 * p + 3]));
        }
    }
}

// ---------------------------------------------------------------------------
// Launch.  CSR build + W2/W3 conversion on a side stream; x/W1 conversion +
// GEMM1 on the main stream (critical path).
// ---------------------------------------------------------------------------
extern "C" void kernel_launch(void* const* d_in, const int* in_sizes, int n_in,
                              void* d_out, int out_size)
{
    const float* x     = (const float*)d_in[0];
    const int*   rows  = (const int*)d_in[1];
    const int*   cols  = (const int*)d_in[2];
    const float* vals  = (const float*)d_in[3];
    const float* W1    = (const float*)d_in[4];
    const float* b1    = (const float*)d_in[5];
    const float* W2    = (const float*)d_in[6];
    const float* b2    = (const float*)d_in[7];
    const float* W3    = (const float*)d_in[8];
    const float* b3    = (const float*)d_in[9];
    const unsigned int* mask1 = (const unsigned int*)d_in[10];
    const unsigned int* mask2 = (const unsigned int*)d_in[11];
    float* out = (float*)d_out;

    const int N = in_sizes[0] / 256;
    const int E = in_sizes[1];

    void *pH = nullptr, *pA = nullptr, *pW = nullptr, *pCnt = nullptr;
    cudaGetSymbolAddress(&pH, g_h16);
    cudaGetSymbolAddress(&pA, g_a16);
    cudaGetSymbolAddress(&pW, g_W16);
    cudaGetSymbolAddress(&pCnt, g_cnt);
    __half* h16 = (__half*)pH;
    __half* a16 = (__half*)pA;
    __half* W16 = (__half*)pW;

    static cudaStream_t s2 = nullptr;
    static cudaEvent_t evFork = nullptr, evJoin = nullptr;
    if (s2 == nullptr) {
        cudaStreamCreateWithFlags(&s2, cudaStreamNonBlocking);
        cudaEventCreateWithFlags(&evFork, cudaEventDisableTiming);
        cudaEventCreateWithFlags(&evJoin, cudaEventDisableTiming);
    }

    // Fork: CSR build + W2/W3 conversion on s2.
    cudaEventRecord(evFork, 0);
    cudaStreamWaitEvent(s2, evFork, 0);
    cudaMemsetAsync(pCnt, 0, (size_t)N * sizeof(int), s2);
    hist_kernel<<<(E + 255) / 256, 256, 0, s2>>>(rows, E);
    scan_kernel<<<1, 1024, 0, s2>>>(N);
    scatter_kernel<<<(E + 255) / 256, 256, 0, s2>>>(rows, cols, vals, E);
    cvt16_kernel<<<(32768 / 4 + 255) / 256, 256, 0, s2>>>(W2, W16 + 65536, 32768 / 4);
    cvt16_kernel<<<(8192 / 4 + 255) / 256, 256, 0, s2>>>(W3, W16 + 98304, 8192 / 4);
    cudaEventRecord(evJoin, s2);

    // Main stream: x + W1 conversion, then GEMM1 (overlaps the CSR build)
    cvt16_kernel<<<(65536 / 4 + 255) / 256, 256>>>(W1, W16, 65536 / 4);
    {
        int n4 = N * 256 / 4;
        cvt16_kernel<<<(n4 + 255) / 256, 256>>>(x, a16, n4);
    }

    dim3 g1((N + 127) / 128, 256 / 128);
    gemm_tc_kernel<256, 256, 512><<<g1, 512>>>(a16, W16, b1, h16, N);

    // Join: SpMM1 needs GEMM1, the CSR, and (transitively) W2/W3.
    cudaStreamWaitEvent(0, evJoin, 0);
    spmm_kernel<256, true, true><<<(N + 7) / 8, 256>>>(h16, mask1, a16, nullptr, N);

    // Layer 2: 256 -> 128
    dim3 g2((N + 127) / 128, 1);
    gemm_tc_kernel<256, 128, 512><<<g2, 512>>>(a16, W16 + 65536, b2, h16, N);
    spmm_kernel<128, true, true><<<(N + 7) / 8, 256>>>(h16, mask2, a16, nullptr, N);

    // Layer 3: 128 -> 64
    dim3 g3((N + 127) / 128, 1);
    gemm_tc_kernel<128, 64, 256><<<g3, 256>>>(a16, W16 + 98304, b3, h16, N);
    spmm_kernel<64, false, false><<<(N + 7) / 8, 256>>>(h16, nullptr, nullptr, out, N);
}